// round 16
// baseline (speedup 1.0000x reference)
#include <cuda_runtime.h>
#include <cstdint>

// TopK per row (B=4096 x D=65536 fp32, k=64), ReLU, scatter into zeros.
// TWO-PHASE split to keep every DRAM stream unidirectional (no read/write
// turnaround):
//   1) zero_kernel  : pure-write zero fill of out (measured 7.07 TB/s).
//   2) select_kernel: pure-read top-k per row (R15's proven plain-LDG loop),
//      exact rank of ~168 candidates in smem, winners scattered DIRECTLY
//      into the zeroed row (kernel boundary orders it after zero_kernel).
// Exact 3-level radix fallback (tie-break lowest index, jax.lax.top_k rule)
// for arbitrary inputs; never triggers on N(0,1) benchmark data.

namespace {

constexpr int TPB    = 512;
constexpr int D_DIM  = 65536;
constexpr int NV     = D_DIM / 4;       // 16384 float4 per row
constexpr int U      = 4;               // float4 per thread per iter
constexpr int ITERS  = NV / (TPB * U);  // 8
constexpr int CAP    = 2048;            // candidate capacity
constexpr float THRESH = 2.8f;          // E[cnt]~168 for N(0,1), >> k=64
constexpr unsigned SMEM_BYTES = 2u * CAP * 4u;   // 16 KB (cand; hist aliases)

__device__ __forceinline__ unsigned orderKey(float f) {
    unsigned u = __float_as_uint(f);
    return u ^ ((u & 0x80000000u) ? 0xFFFFFFFFu : 0x80000000u);
}

// ---------------------------------------------------------------- zero fill
__global__ void __launch_bounds__(TPB)
zero_kernel(float4* __restrict__ out)
{
    float4* rowp = out + (size_t)blockIdx.x * NV;
    const float4 z = make_float4(0.f, 0.f, 0.f, 0.f);
    #pragma unroll 8
    for (int i = threadIdx.x; i < NV; i += TPB)
        __stcs(&rowp[i], z);
}

// ---------------------------------------------------------------- select
__global__ void __launch_bounds__(TPB)
select_kernel(const float* __restrict__ x,
              const int* __restrict__ kptr,
              float* __restrict__ out)
{
    extern __shared__ unsigned smem_u[];
    float*    cval = reinterpret_cast<float*>(smem_u);    // [CAP]
    unsigned* cidx = smem_u + CAP;                        // [CAP]
    unsigned* hist = smem_u;   // fallback alias (cand dead by then)
    __shared__ unsigned s_cnt, s_bin, s_rank;
    __shared__ unsigned s_chunk[TPB + 1];

    const int tid = threadIdx.x;
    const int row = blockIdx.x;
    const unsigned k = (unsigned)__ldg(kptr);

    const float4* rowv = reinterpret_cast<const float4*>(x) + (size_t)row * NV;
    float*        outf = out + (size_t)row * D_DIM;

    if (tid == 0) s_cnt = 0u;
    __syncthreads();

    // ---- Hot pass: pure read stream (plain LDG.128) + rare collect ----
    #pragma unroll
    for (int it = 0; it < ITERS; ++it) {
        const int base = tid + it * TPB * U;
        float4 v[U];
        #pragma unroll
        for (int u = 0; u < U; ++u)
            v[u] = rowv[base + u * TPB];          // plain LDG.E.128

        float m[U];
        #pragma unroll
        for (int u = 0; u < U; ++u)
            m[u] = fmaxf(fmaxf(v[u].x, v[u].y), fmaxf(v[u].z, v[u].w));

        bool any = (m[0] >= THRESH) | (m[1] >= THRESH) |
                   (m[2] >= THRESH) | (m[3] >= THRESH);
        if (any) {                                    // rare per thread
            #pragma unroll
            for (int u = 0; u < U; ++u) {
                if (m[u] >= THRESH) {
                    const int i = base + u * TPB;
                    float vv[4] = {v[u].x, v[u].y, v[u].z, v[u].w};
                    #pragma unroll
                    for (int l = 0; l < 4; ++l) {
                        if (vv[l] >= THRESH) {
                            unsigned p = atomicAdd(&s_cnt, 1u);
                            if (p < CAP) { cval[p] = vv[l]; cidx[p] = (unsigned)(i * 4 + l); }
                        }
                    }
                }
            }
        }
    }
    __syncthreads();

    const unsigned cnt = s_cnt;
    if (cnt >= k && cnt <= CAP) {
        // ---- Exact rank among candidates; scatter into zeroed row ----
        for (unsigned j = (unsigned)tid; j < cnt; j += TPB) {
            const float    vj = cval[j];
            const unsigned ij = cidx[j];
            unsigned rank = 0;
            for (unsigned t = 0; t < cnt; ++t) {
                const float vt = cval[t];
                rank += (vt > vj) || (vt == vj && cidx[t] < ij);
            }
            if (rank < k)
                outf[ij] = fmaxf(vj, 0.0f);
        }
        return;
    }

    // ============== Exact fallback: 3-level radix refinement ==============
    // hist aliases the candidate arrays (dead here). Row already zeroed.
    const float* rowf = reinterpret_cast<const float*>(rowv);
    unsigned need = k;
    unsigned b0, b1, b2;

    // level 0: bits[31:20]
    __syncthreads();
    for (int i = tid; i < 4096; i += TPB) hist[i] = 0u;
    __syncthreads();
    for (int i = tid; i < D_DIM; i += TPB)
        atomicAdd(&hist[orderKey(rowf[i]) >> 20], 1u);
    __syncthreads();
    if (tid == 0) {
        unsigned acc = 0;
        for (int b = 4095; b >= 0; --b) {
            unsigned c = hist[b];
            if (acc + c >= need) { s_bin = (unsigned)b; s_rank = need - acc; break; }
            acc += c;
        }
    }
    __syncthreads();
    b0 = s_bin; need = s_rank;

    // level 1: bits[19:8] restricted to top bits == b0
    for (int i = tid; i < 4096; i += TPB) hist[i] = 0u;
    __syncthreads();
    for (int i = tid; i < D_DIM; i += TPB) {
        unsigned key = orderKey(rowf[i]);
        if ((key >> 20) == b0) atomicAdd(&hist[(key >> 8) & 0xFFFu], 1u);
    }
    __syncthreads();
    if (tid == 0) {
        unsigned acc = 0;
        for (int b = 4095; b >= 0; --b) {
            unsigned c = hist[b];
            if (acc + c >= need) { s_bin = (unsigned)b; s_rank = need - acc; break; }
            acc += c;
        }
    }
    __syncthreads();
    b1 = s_bin; need = s_rank;

    // level 2: bits[7:0] restricted to top 24 bits
    for (int i = tid; i < 256; i += TPB) hist[i] = 0u;
    __syncthreads();
    const unsigned pre24 = (b0 << 12) | b1;
    for (int i = tid; i < D_DIM; i += TPB) {
        unsigned key = orderKey(rowf[i]);
        if ((key >> 8) == pre24) atomicAdd(&hist[key & 0xFFu], 1u);
    }
    __syncthreads();
    if (tid == 0) {
        unsigned acc = 0;
        for (int b = 255; b >= 0; --b) {
            unsigned c = hist[b];
            if (acc + c >= need) { s_bin = (unsigned)b; s_rank = need - acc; break; }
            acc += c;
        }
    }
    __syncthreads();
    b2 = s_bin; need = s_rank;                    // take `need` of key==pivot
    const unsigned pivot = (pre24 << 8) | b2;

    // winners with key > pivot: write directly
    for (int i = tid; i < D_DIM; i += TPB) {
        float v = rowf[i];
        if (orderKey(v) > pivot)
            outf[i] = fmaxf(v, 0.0f);
    }

    // key == pivot: take `need` with SMALLEST indices (jax tie rule)
    {
        const int CHUNK = D_DIM / TPB;   // 128
        unsigned local = 0;
        for (int i = tid * CHUNK; i < (tid + 1) * CHUNK; ++i)
            local += (orderKey(rowf[i]) == pivot);
        s_chunk[tid + 1] = local;
        if (tid == 0) s_chunk[0] = 0;
        __syncthreads();
        if (tid == 0)
            for (int t = 1; t <= TPB; ++t) s_chunk[t] += s_chunk[t - 1];
        __syncthreads();
        unsigned ord = s_chunk[tid];
        for (int i = tid * CHUNK; i < (tid + 1) * CHUNK; ++i) {
            float v = rowf[i];
            if (orderKey(v) == pivot) {
                if (ord < need)
                    outf[i] = fmaxf(v, 0.0f);
                ++ord;
            }
        }
    }
}

} // namespace

extern "C" void kernel_launch(void* const* d_in, const int* in_sizes, int n_in,
                              void* d_out, int out_size)
{
    const float* x   = (const float*)d_in[0];
    const int*   kp  = (const int*)d_in[1];
    float*       out = (float*)d_out;

    const int rows = in_sizes[0] / D_DIM;

    cudaFuncSetAttribute(select_kernel,
                         cudaFuncAttributeMaxDynamicSharedMemorySize, SMEM_BYTES);

    zero_kernel<<<rows, TPB>>>(reinterpret_cast<float4*>(out));
    select_kernel<<<rows, TPB, SMEM_BYTES>>>(x, kp, out);
}

// round 17
// speedup vs baseline: 1.0174x; 1.0174x over previous
#include <cuda_runtime.h>
#include <cstdint>

// TopK per row (B=4096 x D=65536 fp32, k=64), ReLU, scatter into zeros.
// Fused kernel, one CTA per row, BOTH DRAM directions via TMA bulk engines:
//   - writes: 32 x 8KB cp.async.bulk smem->gmem zeros (proven ~7 TB/s path)
//   - reads : 16 x 16KB cp.async.bulk gmem->smem into a 3-deep ring with
//             mbarrier complete_tx, prefetched 2 chunks ahead; threads scan
//             chunks from smem (LDS.128) for threshold candidates.
// LDG is eliminated from the hot path (per-thread load pipe capped at 5.5TB/s
// in R16; bulk engines measured ~7TB/s).
// Exact 3-level radix fallback (tie-break lowest index, jax.lax.top_k rule);
// never triggers on N(0,1) data.

namespace {

constexpr int TPB    = 512;
constexpr int D_DIM  = 65536;
constexpr int ROWB   = D_DIM * 4;        // 256 KB per row
constexpr int ZBYTES = 8 * 1024;         // zero source / write chunk
constexpr int NZCH   = ROWB / ZBYTES;    // 32 write chunks
constexpr int RCH    = 16 * 1024;        // read chunk bytes
constexpr int NRCH   = ROWB / RCH;       // 16 read chunks
constexpr int NBUF   = 3;                // read ring depth
constexpr int CAP    = 1024;             // candidate capacity (E~168)
constexpr float THRESH = 2.8f;
constexpr int FPC    = RCH / 4;          // floats per chunk (4096)
constexpr int VPC    = FPC / 4;          // float4 per chunk (1024)
constexpr unsigned SMEM_BYTES = ZBYTES + NBUF * RCH + 2u * CAP * 4u; // 64 KB

__device__ __forceinline__ unsigned orderKey(float f) {
    unsigned u = __float_as_uint(f);
    return u ^ ((u & 0x80000000u) ? 0xFFFFFFFFu : 0x80000000u);
}

__device__ __forceinline__ uint32_t smem_u32(const void* p) {
    uint32_t a;
    asm("{ .reg .u64 t; cvta.to.shared.u64 t, %1; cvt.u32.u64 %0, t; }"
        : "=r"(a) : "l"(p));
    return a;
}

__device__ __forceinline__ void mbar_wait(uint32_t mbar, uint32_t parity) {
    asm volatile(
        "{\n\t"
        ".reg .pred P1;\n\t"
        "WL%=:\n\t"
        "mbarrier.try_wait.parity.acquire.cta.shared::cta.b64 P1, [%0], %1, 0x989680;\n\t"
        "@P1 bra WD%=;\n\t"
        "bra WL%=;\n\t"
        "WD%=:\n\t"
        "}"
        :: "r"(mbar), "r"(parity) : "memory");
}

__global__ void __launch_bounds__(TPB)
topk_tma2_kernel(const float* __restrict__ x,
                 const int* __restrict__ kptr,
                 float* __restrict__ out)
{
    extern __shared__ unsigned smem_u[];
    char*     smem = reinterpret_cast<char*>(smem_u);
    unsigned* zbuf = smem_u;                                    // [ZBYTES/4]
    char*     rbuf = smem + ZBYTES;                             // [NBUF*RCH]
    float*    cval = reinterpret_cast<float*>(smem + ZBYTES + NBUF * RCH); // [CAP]
    unsigned* cidx = reinterpret_cast<unsigned*>(cval + CAP);   // [CAP]
    unsigned* hist = smem_u;     // fallback alias (everything dead by then)
    __shared__ uint64_t s_mbar[NBUF];
    __shared__ unsigned s_cnt, s_bin, s_rank;
    __shared__ unsigned s_chunk[TPB + 1];

    const int tid = threadIdx.x;
    const int row = blockIdx.x;
    const unsigned k = (unsigned)__ldg(kptr);

    const char* rowsrc = reinterpret_cast<const char*>(x) + (size_t)row * ROWB;
    float*      outf   = out + (size_t)row * D_DIM;

    // ---- Prologue: zero the TMA write source; init read mbarriers ----
    for (int i = tid; i < ZBYTES / 4; i += TPB) zbuf[i] = 0u;
    if (tid == 0) {
        s_cnt = 0u;
        #pragma unroll
        for (int b = 0; b < NBUF; ++b)
            asm volatile("mbarrier.init.shared.b64 [%0], 1;"
                         :: "r"(smem_u32(&s_mbar[b])) : "memory");
    }
    asm volatile("fence.proxy.async.shared::cta;" ::: "memory");
    __syncthreads();

    const uint32_t zs = smem_u32(zbuf);
    const uint32_t rb0 = smem_u32(rbuf);

    if (tid == 0) {
        // background zero writes (bulk_group)
        #pragma unroll
        for (int c = 0; c < NZCH; ++c) {
            const char* dst = reinterpret_cast<const char*>(outf) + (size_t)c * ZBYTES;
            asm volatile(
                "cp.async.bulk.global.shared::cta.bulk_group [%0], [%1], %2;"
                :: "l"(dst), "r"(zs), "r"((unsigned)ZBYTES) : "memory");
        }
        asm volatile("cp.async.bulk.commit_group;" ::: "memory");
        // prefetch read chunks 0 and 1
        #pragma unroll
        for (int c = 0; c < 2; ++c) {
            uint32_t mb = smem_u32(&s_mbar[c]);
            asm volatile("mbarrier.arrive.expect_tx.shared.b64 _, [%0], %1;"
                         :: "r"(mb), "r"((unsigned)RCH) : "memory");
            asm volatile(
                "cp.async.bulk.shared::cluster.global.mbarrier::complete_tx::bytes "
                "[%0], [%1], %2, [%3];"
                :: "r"(rb0 + c * RCH), "l"(rowsrc + (size_t)c * RCH),
                   "r"((unsigned)RCH), "r"(mb) : "memory");
        }
    }
    __syncthreads();

    // ---- Hot loop: consume 16 chunks from the smem ring ----
    for (int c = 0; c < NRCH; ++c) {
        const int buf = c % NBUF;
        // prefetch c+2 into its ring slot (free since its last scan ended
        // before the __syncthreads closing iteration c-1)
        if (tid == 0 && c + 2 < NRCH) {
            const int pb = (c + 2) % NBUF;
            uint32_t mb = smem_u32(&s_mbar[pb]);
            asm volatile("mbarrier.arrive.expect_tx.shared.b64 _, [%0], %1;"
                         :: "r"(mb), "r"((unsigned)RCH) : "memory");
            asm volatile(
                "cp.async.bulk.shared::cluster.global.mbarrier::complete_tx::bytes "
                "[%0], [%1], %2, [%3];"
                :: "r"(rb0 + pb * RCH), "l"(rowsrc + (size_t)(c + 2) * RCH),
                   "r"((unsigned)RCH), "r"(mb) : "memory");
        }

        mbar_wait(smem_u32(&s_mbar[buf]), (unsigned)((c / NBUF) & 1));

        // scan this chunk: 512 threads x 2 float4
        const float4* cb = reinterpret_cast<const float4*>(rbuf + buf * RCH);
        #pragma unroll
        for (int h = 0; h < 2; ++h) {
            const int lane = tid + h * TPB;          // 0..1023
            float4 v = cb[lane];
            float m = fmaxf(fmaxf(v.x, v.y), fmaxf(v.z, v.w));
            if (m >= THRESH) {                        // rare
                const int gi = c * FPC + lane * 4;
                float vv[4] = {v.x, v.y, v.z, v.w};
                #pragma unroll
                for (int l = 0; l < 4; ++l) {
                    if (vv[l] >= THRESH) {
                        unsigned p = atomicAdd(&s_cnt, 1u);
                        if (p < CAP) { cval[p] = vv[l]; cidx[p] = (unsigned)(gi + l); }
                    }
                }
            }
        }
        __syncthreads();   // all scans of `buf` done before tid0 refills it
    }

    // ---- Zero writes must land before winner scatter ----
    if (tid == 0)
        asm volatile("cp.async.bulk.wait_group 0;" ::: "memory");
    __syncthreads();

    const unsigned cnt = s_cnt;
    if (cnt >= k && cnt <= CAP) {
        for (unsigned j = (unsigned)tid; j < cnt; j += TPB) {
            const float    vj = cval[j];
            const unsigned ij = cidx[j];
            unsigned rank = 0;
            for (unsigned t = 0; t < cnt; ++t) {
                const float vt = cval[t];
                rank += (vt > vj) || (vt == vj && cidx[t] < ij);
            }
            if (rank < k)
                outf[ij] = fmaxf(vj, 0.0f);
        }
        return;
    }

    // ============== Exact fallback: 3-level radix refinement ==============
    // All TMA (read+write) complete; smem fully reusable. LDG-based.
    const float* rowf = reinterpret_cast<const float*>(rowsrc);
    unsigned need = k;
    unsigned b0, b1, b2;

    __syncthreads();
    for (int i = tid; i < 4096; i += TPB) hist[i] = 0u;
    __syncthreads();
    for (int i = tid; i < D_DIM; i += TPB)
        atomicAdd(&hist[orderKey(rowf[i]) >> 20], 1u);
    __syncthreads();
    if (tid == 0) {
        unsigned acc = 0;
        for (int b = 4095; b >= 0; --b) {
            unsigned c = hist[b];
            if (acc + c >= need) { s_bin = (unsigned)b; s_rank = need - acc; break; }
            acc += c;
        }
    }
    __syncthreads();
    b0 = s_bin; need = s_rank;

    for (int i = tid; i < 4096; i += TPB) hist[i] = 0u;
    __syncthreads();
    for (int i = tid; i < D_DIM; i += TPB) {
        unsigned key = orderKey(rowf[i]);
        if ((key >> 20) == b0) atomicAdd(&hist[(key >> 8) & 0xFFFu], 1u);
    }
    __syncthreads();
    if (tid == 0) {
        unsigned acc = 0;
        for (int b = 4095; b >= 0; --b) {
            unsigned c = hist[b];
            if (acc + c >= need) { s_bin = (unsigned)b; s_rank = need - acc; break; }
            acc += c;
        }
    }
    __syncthreads();
    b1 = s_bin; need = s_rank;

    for (int i = tid; i < 256; i += TPB) hist[i] = 0u;
    __syncthreads();
    const unsigned pre24 = (b0 << 12) | b1;
    for (int i = tid; i < D_DIM; i += TPB) {
        unsigned key = orderKey(rowf[i]);
        if ((key >> 8) == pre24) atomicAdd(&hist[key & 0xFFu], 1u);
    }
    __syncthreads();
    if (tid == 0) {
        unsigned acc = 0;
        for (int b = 255; b >= 0; --b) {
            unsigned c = hist[b];
            if (acc + c >= need) { s_bin = (unsigned)b; s_rank = need - acc; break; }
            acc += c;
        }
    }
    __syncthreads();
    b2 = s_bin; need = s_rank;
    const unsigned pivot = (pre24 << 8) | b2;

    for (int i = tid; i < D_DIM; i += TPB) {
        float v = rowf[i];
        if (orderKey(v) > pivot)
            outf[i] = fmaxf(v, 0.0f);
    }

    {
        const int CHUNK = D_DIM / TPB;   // 128
        unsigned local = 0;
        for (int i = tid * CHUNK; i < (tid + 1) * CHUNK; ++i)
            local += (orderKey(rowf[i]) == pivot);
        s_chunk[tid + 1] = local;
        if (tid == 0) s_chunk[0] = 0;
        __syncthreads();
        if (tid == 0)
            for (int t = 1; t <= TPB; ++t) s_chunk[t] += s_chunk[t - 1];
        __syncthreads();
        unsigned ord = s_chunk[tid];
        for (int i = tid * CHUNK; i < (tid + 1) * CHUNK; ++i) {
            float v = rowf[i];
            if (orderKey(v) == pivot) {
                if (ord < need)
                    outf[i] = fmaxf(v, 0.0f);
                ++ord;
            }
        }
    }
}

} // namespace

extern "C" void kernel_launch(void* const* d_in, const int* in_sizes, int n_in,
                              void* d_out, int out_size)
{
    const float* x   = (const float*)d_in[0];
    const int*   kp  = (const int*)d_in[1];
    float*       out = (float*)d_out;

    const int rows = in_sizes[0] / D_DIM;

    cudaFuncSetAttribute(topk_tma2_kernel,
                         cudaFuncAttributeMaxDynamicSharedMemorySize, SMEM_BYTES);
    topk_tma2_kernel<<<rows, TPB, SMEM_BYTES>>>(x, kp, out);
}